// round 7
// baseline (speedup 1.0000x reference)
#include <cuda_runtime.h>

// Reference math:
//   y = x @ W.T + b                      (B, OUT)
//   m = max(y, axis=1, keepdims=True)    (B, 1)
//   centered = m - mean(m, axis=1)       == 0 exactly (mean over a size-1 axis)
//   out = gelu_tanh(0)                   == 0 exactly
//
// Output is identically zero for ALL inputs; the GEMM is dead code.
// History: R1 4-block kernel 4.61us (kernel 3.42us). R2 graph-memset 5.12us
// (FAILED — driver memset node slower than user kernel node). R3 1x1024
// kernel: 4.61us end-to-end (quantized tick), kernel 3.14us.
// R6: cut warp count 32 -> 4. One CTA, 128 threads, 8 unrolled STG.128 per
// thread (16KB total). Store-issue cost is ~negligible; CTA schedule/drain
// cost scales with warps. Target: cross the 0.512us timer tick to 4.096us.

__global__ void __launch_bounds__(128, 1)
ModelNew_25056839205334_zero(float4* __restrict__ out) {
    const float4 z = make_float4(0.0f, 0.0f, 0.0f, 0.0f);
    float4* p = out + threadIdx.x;
    // 1024 float4 total = 128 threads x 8 stores, stride 128 float4 (2KB)
    // -> each warp's stores are fully coalesced 512B segments.
#pragma unroll
    for (int i = 0; i < 8; i++) {
        p[i * 128] = z;
    }
}

extern "C" void kernel_launch(void* const* d_in, const int* in_sizes, int n_in,
                              void* d_out, int out_size) {
    (void)d_in; (void)in_sizes; (void)n_in;
    if (out_size == 4096) {
        // Fast path: fixed problem shape (4096 floats = 1024 float4).
        ModelNew_25056839205334_zero<<<1, 128>>>((float4*)d_out);
    } else {
        // Generic fallback (never taken for this shape).
        cudaMemsetAsync(d_out, 0, (size_t)out_size * sizeof(float), 0);
    }
}

// round 8
// speedup vs baseline: 1.2143x; 1.2143x over previous
#include <cuda_runtime.h>

// Reference math:
//   y = x @ W.T + b                      (B, OUT)
//   m = max(y, axis=1, keepdims=True)    (B, 1)
//   centered = m - mean(m, axis=1)       == 0 exactly (mean over a size-1 axis)
//   out = gelu_tanh(0)                   == 0 exactly  (tanh-GELU of 0 is 0)
//
// Output is identically zero for ALL inputs; the 137-GFLOP GEMM is dead code.
//
// Config search (kernel dur from ncu):
//   R1  4 CTA x 256, 1 st/thr   : 3.424us
//   R2  graph memset node       : slower end-to-end (5.12us) — driver path
//   R3  1 CTA x 1024, 1 st/thr  : 3.136us  <-- BEST
//   R6  1 CTA x 128, 8 st/thr   : 3.712us  (drain is store-completion-bound;
//                                           serializing issue hurts)
// Optimum bracketed from both sides. This reverts to R3: all 1024 STG.128s
// enter flight within ~64 issue cycles across 4 SMSPs; remaining ~3us is
// fixed dispatch/drain overhead not addressable from the .cu.

__global__ void __launch_bounds__(1024, 1)
ModelNew_25056839205334_zero(float4* __restrict__ out) {
    // out_size = 4096 floats = 1024 float4; exactly one per thread.
    out[threadIdx.x] = make_float4(0.0f, 0.0f, 0.0f, 0.0f);
}

extern "C" void kernel_launch(void* const* d_in, const int* in_sizes, int n_in,
                              void* d_out, int out_size) {
    (void)d_in; (void)in_sizes; (void)n_in;
    if (out_size == 4096) {
        ModelNew_25056839205334_zero<<<1, 1024>>>((float4*)d_out);
    } else {
        // Generic fallback (never taken for this problem's fixed shape).
        cudaMemsetAsync(d_out, 0, (size_t)out_size * sizeof(float), 0);
    }
}

// round 11
// speedup vs baseline: 1.3077x; 1.0769x over previous
#include <cuda_runtime.h>

// Reference math:
//   y = x @ W.T + b                      (B, OUT)
//   m = max(y, axis=1, keepdims=True)    (B, 1)
//   centered = m - mean(m, axis=1)       == 0 exactly (mean over a size-1 axis)
//   out = gelu_tanh(0)                   == 0 exactly  (tanh-GELU of 0 is 0)
//
// Output is identically zero for ALL inputs; the 137-GFLOP GEMM is dead code.
// Fastest correct kernel = one graph node writing 4096 zero floats (16 KB).
//
// Config search, with noise calibration (R8 re-ran R3's exact source):
//   R3  1 CTA x 1024, 1 st/thr  : kernel 3.136us | end-to-end 4.608us
//   R8  (identical source)      : kernel 3.520us | end-to-end 4.928us
//   R1  4 CTA x 256             : kernel 3.424us
//   R6  1 CTA x 128, 8 st/thr   : kernel 3.712us
//   R2  graph memset node       : 5.12us end-to-end (real regression)
// => all kernel-node shapes indistinguishable within ±0.4us noise; memset
//    node is strictly worse. Every ncu throughput axis <= 0.3%. Remaining
//    time is fixed single-node dispatch + graph-replay overhead, not
//    addressable from the .cu. TERMINAL KERNEL.

__global__ void __launch_bounds__(1024, 1)
ModelNew_25056839205334_zero(float4* __restrict__ out) {
    // out_size = 4096 floats = 1024 float4; exactly one STG.128 per thread.
    out[threadIdx.x] = make_float4(0.0f, 0.0f, 0.0f, 0.0f);
}

extern "C" void kernel_launch(void* const* d_in, const int* in_sizes, int n_in,
                              void* d_out, int out_size) {
    (void)d_in; (void)in_sizes; (void)n_in;
    if (out_size == 4096) {
        ModelNew_25056839205334_zero<<<1, 1024>>>((float4*)d_out);
    } else {
        // Generic fallback (never taken for this problem's fixed shape).
        cudaMemsetAsync(d_out, 0, (size_t)out_size * sizeof(float), 0);
    }
}